// round 13
// baseline (speedup 1.0000x reference)
#include <cuda_runtime.h>
#include <math.h>

#define BATCH   64
#define VDIM    16384
#define FDIM    32
#define CDIM    4
#define NSPLIT  32
#define ROWS_PER_SPLIT (VDIM / NSPLIT)   // 512
#define GROUPS_PER_SPLIT (ROWS_PER_SPLIT / 4)  // 128 (4-row groups)

// Deterministic scratch (no float atomics): [B][NSPLIT][2][F]
__device__ float g_scratch[BATCH * NSPLIT * 2 * FDIM];
// rank[b][f] = output column for input column f (inverse permutation)
__device__ __align__(16) int g_rank[BATCH * FDIM];

// ---------------------------------------------------------------------------
// Pass 1: split reduction, fully vectorized.
// Lane l: row-in-group r = l/8, quad q = l%8 (columns 4q..4q+3).
// One LDG.128 per lane per 4-row group => 512B per warp per load instr.
// ---------------------------------------------------------------------------
__global__ void __launch_bounds__(256)
reduce_kernel(const float4* __restrict__ fracs, const float2* __restrict__ feats)
{
    const int b     = blockIdx.y;
    const int split = blockIdx.x;
    const int lane  = threadIdx.x & 31;
    const int warp  = threadIdx.x >> 5;
    const int q     = lane & 7;
    const int r     = lane >> 3;

    const float4* __restrict__ fb = fracs + (size_t)b * VDIM * 8;  // 8 float4/row
    const float2* __restrict__ eb = feats + (size_t)b * VDIM * 2;  // 2 float2/row
    const int g0 = split * GROUPS_PER_SPLIT;

    float4 s  = make_float4(0.f, 0.f, 0.f, 0.f);
    float4 ws = make_float4(0.f, 0.f, 0.f, 0.f);

    #pragma unroll 4
    for (int g = warp; g < GROUPS_PER_SPLIT; g += 8) {
        const int v = (g0 + g) * 4 + r;
        float4 x  = __ldg(fb + (size_t)v * 8 + q);
        float2 ee = __ldg(eb + (size_t)v * 2);        // (e, eta) broadcast in group
        const float e  = ee.x;
        const float ew = ee.x * ee.y;
        s.x  += e  * x.x;  s.y  += e  * x.y;  s.z  += e  * x.z;  s.w  += e  * x.w;
        ws.x += ew * x.x;  ws.y += ew * x.y;  ws.z += ew * x.z;  ws.w += ew * x.w;
    }

    // Combine the 4 row-groups: xor-shuffle over lane bits 3,4 (fixed order).
    #pragma unroll
    for (int off = 8; off <= 16; off <<= 1) {
        s.x  += __shfl_xor_sync(0xffffffffu, s.x,  off);
        s.y  += __shfl_xor_sync(0xffffffffu, s.y,  off);
        s.z  += __shfl_xor_sync(0xffffffffu, s.z,  off);
        s.w  += __shfl_xor_sync(0xffffffffu, s.w,  off);
        ws.x += __shfl_xor_sync(0xffffffffu, ws.x, off);
        ws.y += __shfl_xor_sync(0xffffffffu, ws.y, off);
        ws.z += __shfl_xor_sync(0xffffffffu, ws.z, off);
        ws.w += __shfl_xor_sync(0xffffffffu, ws.w, off);
    }

    __shared__ float smS[8][FDIM];
    __shared__ float smW[8][FDIM];
    if (r == 0) {                    // lanes 0..7 hold totals for quad q
        *reinterpret_cast<float4*>(&smS[warp][q * 4]) = s;
        *reinterpret_cast<float4*>(&smW[warp][q * 4]) = ws;
    }
    __syncthreads();

    if (warp == 0) {
        float a = 0.f, wa = 0.f;
        #pragma unroll
        for (int w = 0; w < 8; w++) {
            a  += smS[w][lane];
            wa += smW[w][lane];
        }
        float* dst = g_scratch + (size_t)(b * NSPLIT + split) * 2 * FDIM;
        dst[lane]        = a;
        dst[FDIM + lane] = wa;
    }
}

// ---------------------------------------------------------------------------
// Pass 2: combine splits (fixed order), weighted etas, stable counting-rank
// (matches jax.lax.top_k(-we) tie semantics). Store the INVERSE permutation:
// rank[f] = output column of input column f. One warp per batch.
// ---------------------------------------------------------------------------
__global__ void sort_kernel()
{
    const int b = blockIdx.x;
    const int f = threadIdx.x;   // 32 threads

    float s = 0.f, ws = 0.f;
    for (int sp = 0; sp < NSPLIT; sp++) {
        const float* src = g_scratch + (size_t)(b * NSPLIT + sp) * 2 * FDIM;
        s  += src[f];
        ws += src[FDIM + f];
    }
    float we = ws / (s + 1e-7f);
    we = (fabsf(we) > 0.1f) ? we : 500.0f;

    // rank = #{j : we_j < we_f  or (we_j == we_f and j < f)}  (stable ascending)
    int rank = 0;
    #pragma unroll
    for (int j = 0; j < FDIM; j++) {
        float wj = __shfl_sync(0xffffffffu, we, j);
        rank += (int)((wj < we) || (wj == we && j < f));
    }
    g_rank[b * FDIM + f] = rank;
}

// ---------------------------------------------------------------------------
// Pass 3: permute. LDG.128 of raw data, scatter STG.32 within the 128B
// output row: out[b,v,rank[j]] = fracs[b,v,j]. Loads fully vectorized.
// ---------------------------------------------------------------------------
__global__ void __launch_bounds__(256)
gather_kernel(const float4* __restrict__ fracs, float* __restrict__ out)
{
    const int b    = blockIdx.y;
    const int lane = threadIdx.x & 31;
    const int q    = lane & 7;
    const int r    = lane >> 3;
    const int gw   = blockIdx.x * 8 + (threadIdx.x >> 5);
    const int nw   = gridDim.x * 8;

    // output columns for this lane's 4 raw input columns (4q..4q+3)
    const int4 rk = *reinterpret_cast<const int4*>(&g_rank[b * FDIM + 4 * q]);

    const float4* __restrict__ src = fracs + (size_t)b * VDIM * 8;
    float*        __restrict__ dst = out   + (size_t)b * VDIM * FDIM;

    #pragma unroll 4
    for (int g = gw; g < VDIM / 4; g += nw) {
        const int v = g * 4 + r;
        float4 x = __ldg(src + (size_t)v * 8 + q);
        float* drow = dst + (size_t)v * FDIM;
        drow[rk.x] = x.x;
        drow[rk.y] = x.y;
        drow[rk.z] = x.z;
        drow[rk.w] = x.w;
    }
}

// ---------------------------------------------------------------------------
extern "C" void kernel_launch(void* const* d_in, const int* in_sizes, int n_in,
                              void* d_out, int out_size)
{
    const float4* fracs = (const float4*)d_in[0];   // [64,16384,32] f32
    const float2* feats = (const float2*)d_in[1];   // [64,16384,4]  f32
    float*        out   = (float*)d_out;            // [64,16384,32] f32

    dim3 g1(NSPLIT, BATCH);
    reduce_kernel<<<g1, 256>>>(fracs, feats);

    sort_kernel<<<BATCH, 32>>>();

    dim3 g3(32, BATCH);                              // 256 warps/batch
    gather_kernel<<<g3, 256>>>(fracs, out);
}

// round 14
// speedup vs baseline: 1.0625x; 1.0625x over previous
#include <cuda_runtime.h>
#include <math.h>

#define BATCH   64
#define VDIM    16384
#define FDIM    32
#define NSPLIT  16
#define ROWS_PER_SPLIT (VDIM / NSPLIT)          // 1024
#define GROUPS_PER_SPLIT (ROWS_PER_SPLIT / 4)   // 256 (4-row groups)
#define NGROUPS (VDIM / 4)                       // 4096 per batch

// Deterministic scratch (no float atomics): [B][NSPLIT][2][F]
__device__ float g_scratch[BATCH * NSPLIT * 2 * FDIM];

// ---------------------------------------------------------------------------
// Pass 1: split reduction, fully vectorized, single-wave grid (1024 blocks).
// Lane l: row-in-group r = l/8, quad q = l%8 (columns 4q..4q+3).
// Streams fracs in ASCENDING order so the tail stays resident in L2 for
// pass 2's descending traversal.
// ---------------------------------------------------------------------------
__global__ void __launch_bounds__(256)
reduce_kernel(const float4* __restrict__ fracs, const float2* __restrict__ feats)
{
    const int b     = blockIdx.y;
    const int split = blockIdx.x;
    const int lane  = threadIdx.x & 31;
    const int warp  = threadIdx.x >> 5;
    const int q     = lane & 7;
    const int r     = lane >> 3;

    const float4* __restrict__ fb = fracs + (size_t)b * VDIM * 8;  // 8 float4/row
    const float2* __restrict__ eb = feats + (size_t)b * VDIM * 2;  // 2 float2/row
    const int g0 = split * GROUPS_PER_SPLIT;

    float4 s  = make_float4(0.f, 0.f, 0.f, 0.f);
    float4 ws = make_float4(0.f, 0.f, 0.f, 0.f);

    #pragma unroll 4
    for (int g = warp; g < GROUPS_PER_SPLIT; g += 8) {
        const int v = (g0 + g) * 4 + r;
        float4 x  = __ldg(fb + (size_t)v * 8 + q);      // keep cached for pass 2
        float2 ee = __ldcs(eb + (size_t)v * 2);         // streamed once
        const float e  = ee.x;
        const float ew = ee.x * ee.y;
        s.x  += e  * x.x;  s.y  += e  * x.y;  s.z  += e  * x.z;  s.w  += e  * x.w;
        ws.x += ew * x.x;  ws.y += ew * x.y;  ws.z += ew * x.z;  ws.w += ew * x.w;
    }

    // Combine the 4 row-groups: xor-shuffle over lane bits 3,4 (fixed order).
    #pragma unroll
    for (int off = 8; off <= 16; off <<= 1) {
        s.x  += __shfl_xor_sync(0xffffffffu, s.x,  off);
        s.y  += __shfl_xor_sync(0xffffffffu, s.y,  off);
        s.z  += __shfl_xor_sync(0xffffffffu, s.z,  off);
        s.w  += __shfl_xor_sync(0xffffffffu, s.w,  off);
        ws.x += __shfl_xor_sync(0xffffffffu, ws.x, off);
        ws.y += __shfl_xor_sync(0xffffffffu, ws.y, off);
        ws.z += __shfl_xor_sync(0xffffffffu, ws.z, off);
        ws.w += __shfl_xor_sync(0xffffffffu, ws.w, off);
    }

    __shared__ float smS[8][FDIM];
    __shared__ float smW[8][FDIM];
    if (r == 0) {                    // lanes 0..7 hold totals for quad q
        *reinterpret_cast<float4*>(&smS[warp][q * 4]) = s;
        *reinterpret_cast<float4*>(&smW[warp][q * 4]) = ws;
    }
    __syncthreads();

    if (warp == 0) {
        float a = 0.f, wa = 0.f;
        #pragma unroll
        for (int w = 0; w < 8; w++) {
            a  += smS[w][lane];
            wa += smW[w][lane];
        }
        float* dst = g_scratch + (size_t)(b * NSPLIT + split) * 2 * FDIM;
        dst[lane]        = a;
        dst[FDIM + lane] = wa;
    }
}

// ---------------------------------------------------------------------------
// Pass 2 (fused sort + permute):
//  - warp 0 recomputes weighted etas from g_scratch (fixed split order ->
//    deterministic) and the stable counting-rank matching
//    jax.lax.top_k(-we) tie semantics; rank[f] = output column of input col f.
//  - all warps then permute, traversing DESCENDING (b and v) so the data
//    reduce_kernel touched last (still in L2) is read first.
//  - __ldcs / __stcs: read-once data and write-only output marked
//    evict-first so they don't flush the still-useful fracs tail from L2.
// ---------------------------------------------------------------------------
__global__ void __launch_bounds__(256)
gather_kernel(const float4* __restrict__ fracs, float* __restrict__ out)
{
    __shared__ int s_rank[FDIM];

    const int b = (BATCH - 1) - blockIdx.y;   // reversed batch order

    if (threadIdx.x < 32) {
        const int f = threadIdx.x;
        float s = 0.f, ws = 0.f;
        #pragma unroll
        for (int sp = 0; sp < NSPLIT; sp++) {
            const float* src = g_scratch + (size_t)(b * NSPLIT + sp) * 2 * FDIM;
            s  += src[f];
            ws += src[FDIM + f];
        }
        float we = ws / (s + 1e-7f);
        we = (fabsf(we) > 0.1f) ? we : 500.0f;

        // rank = #{j : we_j < we_f or (we_j == we_f and j < f)} (stable asc.)
        int rank = 0;
        #pragma unroll
        for (int j = 0; j < FDIM; j++) {
            float wj = __shfl_sync(0xffffffffu, we, j);
            rank += (int)((wj < we) || (wj == we && j < f));
        }
        s_rank[f] = rank;
    }
    __syncthreads();

    const int lane = threadIdx.x & 31;
    const int q    = lane & 7;
    const int r    = lane >> 3;
    const int wi   = blockIdx.x * 8 + (threadIdx.x >> 5);
    const int nw   = gridDim.x * 8;

    // output columns for this lane's 4 raw input columns (4q..4q+3)
    const int4 rk = *reinterpret_cast<const int4*>(&s_rank[4 * q]);

    const float4* __restrict__ src = fracs + (size_t)b * VDIM * 8;
    float*        __restrict__ dst = out   + (size_t)b * VDIM * FDIM;

    // descending grid-stride over 4-row groups: hottest L2 lines first
    #pragma unroll 4
    for (int g = NGROUPS - 1 - wi; g >= 0; g -= nw) {
        const int v = g * 4 + r;
        float4 x = __ldcs(src + (size_t)v * 8 + q);
        float* drow = dst + (size_t)v * FDIM;
        __stcs(drow + rk.x, x.x);
        __stcs(drow + rk.y, x.y);
        __stcs(drow + rk.z, x.z);
        __stcs(drow + rk.w, x.w);
    }
}

// ---------------------------------------------------------------------------
extern "C" void kernel_launch(void* const* d_in, const int* in_sizes, int n_in,
                              void* d_out, int out_size)
{
    const float4* fracs = (const float4*)d_in[0];   // [64,16384,32] f32
    const float2* feats = (const float2*)d_in[1];   // [64,16384,4]  f32
    float*        out   = (float*)d_out;            // [64,16384,32] f32

    dim3 g1(NSPLIT, BATCH);    // 1024 blocks — single wave
    reduce_kernel<<<g1, 256>>>(fracs, feats);

    dim3 g2(18, BATCH);        // 1152 blocks — single wave
    gather_kernel<<<g2, 256>>>(fracs, out);
}